// round 4
// baseline (speedup 1.0000x reference)
#include <cuda_runtime.h>

// Problem constants
#define Bn    8
#define NN    2048
#define FINx  512
#define FOUTx 256
#define MTOT  (Bn*NN)          // 16384
#define ALPHAc 0.2f
#define NEGc  (-9e15f)

// ---------------- scratch (device globals: allocation-free) ----------------
__device__ float g_h [MTOT*FOUTx];            // feat@W
__device__ float g_h1[MTOT*FOUTx];            // feat@W1
__device__ float g_g [MTOT*FOUTx];            // h@a12
__device__ float g_h2[MTOT*FOUTx];            // fa@W2
__device__ float g_Ax[MTOT];
__device__ float g_Ay[MTOT];
__device__ float g_e1[MTOT*8];
__device__ float g_e2[MTOT*8];
__device__ float g_S [(size_t)Bn*NN*NN];      // logits / probs (134 MB)
__device__ float g_fa[(size_t)MTOT*FINx];     // feat_agg

// ---------------- generic tiled SGEMM: C = A @ B (or A @ B^T) --------------
// BM=128, BN=64, BK=16, 256 threads, 8x4 microtile.
// EPI==1: scores epilogue (+Ay[row] +Ax[col], leaky relu, adj mask).
template<bool TRANSB, int EPI>
__global__ void __launch_bounds__(256)
gemm_k(const float* __restrict__ A, const float* __restrict__ Bm,
       float* __restrict__ C, int M, int N, int K,
       size_t sA, size_t sB, size_t sC,
       const float* __restrict__ Ax, const float* __restrict__ Ay,
       const int* __restrict__ adj)
{
    constexpr int BM = 128, BN = 64, BK = 16;
    __shared__ float As[BK][BM + 4];
    __shared__ float Bs[BK][BN + 4];

    const int b = blockIdx.z;
    A  += (size_t)b * sA;
    Bm += (size_t)b * sB;
    C  += (size_t)b * sC;

    const int m0 = blockIdx.y * BM;
    const int n0 = blockIdx.x * BN;
    const int tid = threadIdx.x;
    const int tx = tid & 15;          // 0..15 -> 4 cols each
    const int ty = tid >> 4;          // 0..15 -> 8 rows each
    const int arow = tid >> 2;        // 0..63
    const int acol = (tid & 3) * 4;   // 0,4,8,12
    const int brow = tid >> 4;        // 0..15
    const int bcol = (tid & 15) * 4;  // 0..60

    float acc[8][4] = {};

    for (int k0 = 0; k0 < K; k0 += BK) {
        // A tile: 128 rows x 16 cols, two float4 per thread
        float4 a0  = *(const float4*)(A + (size_t)(m0 + arow)      * K + k0 + acol);
        float4 a1v = *(const float4*)(A + (size_t)(m0 + arow + 64) * K + k0 + acol);
        As[acol+0][arow]    = a0.x;  As[acol+1][arow]    = a0.y;
        As[acol+2][arow]    = a0.z;  As[acol+3][arow]    = a0.w;
        As[acol+0][arow+64] = a1v.x; As[acol+1][arow+64] = a1v.y;
        As[acol+2][arow+64] = a1v.z; As[acol+3][arow+64] = a1v.w;

        if (!TRANSB) {
            // B tile: 16 rows x 64 cols
            float4 bv = *(const float4*)(Bm + (size_t)(k0 + brow) * N + n0 + bcol);
            Bs[brow][bcol+0] = bv.x; Bs[brow][bcol+1] = bv.y;
            Bs[brow][bcol+2] = bv.z; Bs[brow][bcol+3] = bv.w;
        } else {
            // B is N x K row-major; need Bs[k][n] = Bm[n0+n][k0+k]
            float4 bv = *(const float4*)(Bm + (size_t)(n0 + arow) * K + k0 + acol);
            Bs[acol+0][arow] = bv.x; Bs[acol+1][arow] = bv.y;
            Bs[acol+2][arow] = bv.z; Bs[acol+3][arow] = bv.w;
        }
        __syncthreads();

        #pragma unroll
        for (int k = 0; k < BK; k++) {
            float4 ra0 = *(const float4*)&As[k][ty * 8];
            float4 ra1 = *(const float4*)&As[k][ty * 8 + 4];
            float4 rb  = *(const float4*)&Bs[k][tx * 4];
            float ra[8] = {ra0.x, ra0.y, ra0.z, ra0.w, ra1.x, ra1.y, ra1.z, ra1.w};
            float rv[4] = {rb.x, rb.y, rb.z, rb.w};
            #pragma unroll
            for (int i = 0; i < 8; i++)
                #pragma unroll
                for (int j = 0; j < 4; j++)
                    acc[i][j] += ra[i] * rv[j];
        }
        __syncthreads();
    }

    #pragma unroll
    for (int i = 0; i < 8; i++) {
        const int m = m0 + ty * 8 + i;
        #pragma unroll
        for (int j = 0; j < 4; j++) {
            const int n = n0 + tx * 4 + j;
            float v = acc[i][j];
            if (EPI == 1) {
                v += Ay[b * NN + m] + Ax[b * NN + n];
                v = (v > 0.f) ? v : ALPHAc * v;
                v = (adj[(size_t)b * NN * NN + (size_t)m * NN + n] > 0) ? v : NEGc;
            }
            C[(size_t)m * N + n] = v;
        }
    }
}

// --------- Ax = h@a1, Ay = h@a2, e1[e] = feat row . L_w[e] (warp/row) -------
__global__ void small1_k(const float* __restrict__ h, const float* __restrict__ feat,
                         const float* __restrict__ a1, const float* __restrict__ a2,
                         const float* __restrict__ Lw,
                         float* __restrict__ Ax, float* __restrict__ Ay,
                         float* __restrict__ e1)
{
    const int warp = (blockIdx.x * blockDim.x + threadIdx.x) >> 5;
    const int lane = threadIdx.x & 31;
    if (warp >= MTOT) return;

    const float* hr = h + (size_t)warp * FOUTx;
    float sx = 0.f, sy = 0.f;
    for (int k = lane; k < FOUTx; k += 32) {
        const float f = hr[k];
        sx += f * a1[k];
        sy += f * a2[k];
    }
    const float* fr = feat + (size_t)warp * FINx;
    float acc[5] = {0.f, 0.f, 0.f, 0.f, 0.f};
    for (int k = lane; k < FINx; k += 32) {
        const float f = fr[k];
        #pragma unroll
        for (int e = 0; e < 5; e++) acc[e] += f * Lw[e * FINx + k];
    }
    #pragma unroll
    for (int off = 16; off; off >>= 1) {
        sx += __shfl_xor_sync(0xffffffffu, sx, off);
        sy += __shfl_xor_sync(0xffffffffu, sy, off);
        #pragma unroll
        for (int e = 0; e < 5; e++) acc[e] += __shfl_xor_sync(0xffffffffu, acc[e], off);
    }
    if (lane == 0) {
        Ax[warp] = sx;
        Ay[warp] = sy;
        #pragma unroll
        for (int e = 0; e < 5; e++) e1[warp * 8 + e] = acc[e];
    }
}

// --------- e2[e] = feat_agg row . R_w[e] -----------------------------------
__global__ void small2_k(const float* __restrict__ fa, const float* __restrict__ Rw,
                         float* __restrict__ e2)
{
    const int warp = (blockIdx.x * blockDim.x + threadIdx.x) >> 5;
    const int lane = threadIdx.x & 31;
    if (warp >= MTOT) return;

    const float* fr = fa + (size_t)warp * FINx;
    float acc[5] = {0.f, 0.f, 0.f, 0.f, 0.f};
    for (int k = lane; k < FINx; k += 32) {
        const float f = fr[k];
        #pragma unroll
        for (int e = 0; e < 5; e++) acc[e] += f * Rw[e * FINx + k];
    }
    #pragma unroll
    for (int off = 16; off; off >>= 1) {
        #pragma unroll
        for (int e = 0; e < 5; e++) acc[e] += __shfl_xor_sync(0xffffffffu, acc[e], off);
    }
    if (lane == 0) {
        #pragma unroll
        for (int e = 0; e < 5; e++) e2[warp * 8 + e] = acc[e];
    }
}

// --------- row softmax over N=2048, in place --------------------------------
__global__ void __launch_bounds__(256)
softmax_k(float* __restrict__ S)
{
    float* p = S + (size_t)blockIdx.x * NN;
    const int t = threadIdx.x;
    float v[8];
    float mx = -3.4e38f;
    #pragma unroll
    for (int i = 0; i < 8; i++) { v[i] = p[t + i * 256]; mx = fmaxf(mx, v[i]); }

    __shared__ float red[256];
    red[t] = mx; __syncthreads();
    #pragma unroll
    for (int s = 128; s > 0; s >>= 1) {
        if (t < s) red[t] = fmaxf(red[t], red[t + s]);
        __syncthreads();
    }
    mx = red[0];
    __syncthreads();

    float sum = 0.f;
    #pragma unroll
    for (int i = 0; i < 8; i++) { v[i] = __expf(v[i] - mx); sum += v[i]; }
    red[t] = sum; __syncthreads();
    #pragma unroll
    for (int s = 128; s > 0; s >>= 1) {
        if (t < s) red[t] += red[t + s];
        __syncthreads();
    }
    const float inv = 1.0f / red[0];
    #pragma unroll
    for (int i = 0; i < 8; i++) p[t + i * 256] = v[i] * inv;
}

// --------- out = h1 + h2 + e1^T B_w[o] e2 ----------------------------------
__global__ void __launch_bounds__(256)
final_k(const float* __restrict__ h1, const float* __restrict__ h2,
        const float* __restrict__ e1, const float* __restrict__ e2,
        const float* __restrict__ Bw, float* __restrict__ out)
{
    const int m = blockIdx.x;
    const int o = threadIdx.x;   // 0..255
    __shared__ float s1[8], s2[8];
    if (o < 5) { s1[o] = e1[m * 8 + o]; s2[o] = e2[m * 8 + o]; }
    __syncthreads();

    const float* bw = Bw + o * 25;
    float s = 0.f;
    #pragma unroll
    for (int i = 0; i < 5; i++) {
        const float ei = s1[i];
        #pragma unroll
        for (int j = 0; j < 5; j++) s += ei * bw[i * 5 + j] * s2[j];
    }
    const size_t idx = (size_t)m * FOUTx + o;
    out[idx] = h1[idx] + h2[idx] + s;
}

// ---------------------------------------------------------------------------
extern "C" void kernel_launch(void* const* d_in, const int* in_sizes, int n_in,
                              void* d_out, int out_size)
{
    const float* feat = (const float*)d_in[0];
    const int*   adj  = (const int*)  d_in[1];
    const float* W    = (const float*)d_in[2];
    const float* W1   = (const float*)d_in[3];
    const float* W2   = (const float*)d_in[4];
    const float* a1   = (const float*)d_in[5];
    const float* a2   = (const float*)d_in[6];
    const float* a12  = (const float*)d_in[7];
    const float* Lw   = (const float*)d_in[8];
    const float* Rw   = (const float*)d_in[9];
    const float* Bw   = (const float*)d_in[10];
    float* out = (float*)d_out;

    float *h, *h1, *g, *h2, *Ax, *Ay, *e1, *e2, *S, *fa;
    cudaGetSymbolAddress((void**)&h,  g_h);
    cudaGetSymbolAddress((void**)&h1, g_h1);
    cudaGetSymbolAddress((void**)&g,  g_g);
    cudaGetSymbolAddress((void**)&h2, g_h2);
    cudaGetSymbolAddress((void**)&Ax, g_Ax);
    cudaGetSymbolAddress((void**)&Ay, g_Ay);
    cudaGetSymbolAddress((void**)&e1, g_e1);
    cudaGetSymbolAddress((void**)&e2, g_e2);
    cudaGetSymbolAddress((void**)&S,  g_S);
    cudaGetSymbolAddress((void**)&fa, g_fa);

    const dim3 blk(256);

    // h = feat @ W ; h1 = feat @ W1
    gemm_k<false,0><<<dim3(FOUTx/64, MTOT/128, 1), blk>>>(
        feat, W,  h,  MTOT, FOUTx, FINx, 0, 0, 0, nullptr, nullptr, nullptr);
    gemm_k<false,0><<<dim3(FOUTx/64, MTOT/128, 1), blk>>>(
        feat, W1, h1, MTOT, FOUTx, FINx, 0, 0, 0, nullptr, nullptr, nullptr);

    // Ax, Ay, e1
    small1_k<<<MTOT/8, 256>>>(h, feat, a1, a2, Lw, Ax, Ay, e1);

    // g = h @ a12
    gemm_k<false,0><<<dim3(FOUTx/64, MTOT/128, 1), blk>>>(
        h, a12, g, MTOT, FOUTx, FOUTx, 0, 0, 0, nullptr, nullptr, nullptr);

    // S[b,i,j] = leaky(Ax[j]+Ay[i]+g_i.h_j) masked by adj  (batched NT GEMM)
    gemm_k<true,1><<<dim3(NN/64, NN/128, Bn), blk>>>(
        g, h, S, NN, NN, FOUTx,
        (size_t)NN*FOUTx, (size_t)NN*FOUTx, (size_t)NN*NN, Ax, Ay, adj);

    // row softmax (in place)
    softmax_k<<<MTOT, 256>>>(S);

    // feat_agg = P @ feat  (batched NN GEMM)
    gemm_k<false,0><<<dim3(FINx/64, NN/128, Bn), blk>>>(
        S, feat, fa, NN, FINx, NN,
        (size_t)NN*NN, (size_t)NN*FINx, (size_t)NN*FINx, nullptr, nullptr, nullptr);

    // e2
    small2_k<<<MTOT/8, 256>>>(fa, Rw, e2);

    // h2 = feat_agg @ W2
    gemm_k<false,0><<<dim3(FOUTx/64, MTOT/128, 1), blk>>>(
        fa, W2, h2, MTOT, FOUTx, FINx, 0, 0, 0, nullptr, nullptr, nullptr);

    // out = h1 + h2 + bilinear(e1, B_w, e2)
    final_k<<<MTOT, 256>>>(h1, h2, e1, e2, Bw, out);
}

// round 5
// speedup vs baseline: 1.0545x; 1.0545x over previous
#include <cuda_runtime.h>

// Problem constants
#define Bn    8
#define NN    2048
#define FINx  512
#define FOUTx 256
#define MTOT  (Bn*NN)          // 16384
#define ALPHAc 0.2f
#define NEGc  (-9e15f)

// ---------------- scratch (device globals: allocation-free) ----------------
__device__ float g_h [MTOT*FOUTx];            // feat@W
__device__ float g_h1[MTOT*FOUTx];            // feat@W1
__device__ float g_g [MTOT*FOUTx];            // h@a12
__device__ float g_h2[MTOT*FOUTx];            // fa@W2
__device__ float g_Ax[MTOT];
__device__ float g_Ay[MTOT];
__device__ float g_e1[MTOT*8];
__device__ float g_e2[MTOT*8];
__device__ float g_S [(size_t)Bn*NN*NN];      // logits / probs (134 MB)
__device__ float g_fa[(size_t)MTOT*FINx];     // feat_agg

// ---------------- generic tiled SGEMM: C = A @ B (or A @ B^T) --------------
// BM=128, BN=64, BK=16, 256 threads, 8x4 microtile.
// EPI==1: scores epilogue (+Ay[row] +Ax[col], leaky relu, adj mask).
template<bool TRANSB, int EPI>
__global__ void __launch_bounds__(256)
gemm_k(const float* __restrict__ A, const float* __restrict__ Bm,
       float* __restrict__ C, int M, int N, int K,
       size_t sA, size_t sB, size_t sC,
       const float* __restrict__ Ax, const float* __restrict__ Ay,
       const int* __restrict__ adj)
{
    constexpr int BM = 128, BN = 64, BK = 16;
    __shared__ float As[BK][BM + 4];
    __shared__ float Bs[BK][BN + 4];

    const int b = blockIdx.z;
    A  += (size_t)b * sA;
    Bm += (size_t)b * sB;
    C  += (size_t)b * sC;

    const int m0 = blockIdx.y * BM;
    const int n0 = blockIdx.x * BN;
    const int tid = threadIdx.x;
    const int tx = tid & 15;          // 0..15 -> 4 cols each
    const int ty = tid >> 4;          // 0..15 -> 8 rows each
    const int arow = tid >> 2;        // 0..63
    const int acol = (tid & 3) * 4;   // 0,4,8,12
    const int brow = tid >> 4;        // 0..15
    const int bcol = (tid & 15) * 4;  // 0..60

    float acc[8][4] = {};

    for (int k0 = 0; k0 < K; k0 += BK) {
        // A tile: 128 rows x 16 cols, two float4 per thread
        float4 a0  = *(const float4*)(A + (size_t)(m0 + arow)      * K + k0 + acol);
        float4 a1v = *(const float4*)(A + (size_t)(m0 + arow + 64) * K + k0 + acol);
        As[acol+0][arow]    = a0.x;  As[acol+1][arow]    = a0.y;
        As[acol+2][arow]    = a0.z;  As[acol+3][arow]    = a0.w;
        As[acol+0][arow+64] = a1v.x; As[acol+1][arow+64] = a1v.y;
        As[acol+2][arow+64] = a1v.z; As[acol+3][arow+64] = a1v.w;

        if (!TRANSB) {
            // B tile: 16 rows x 64 cols
            float4 bv = *(const float4*)(Bm + (size_t)(k0 + brow) * N + n0 + bcol);
            Bs[brow][bcol+0] = bv.x; Bs[brow][bcol+1] = bv.y;
            Bs[brow][bcol+2] = bv.z; Bs[brow][bcol+3] = bv.w;
        } else {
            // B is N x K row-major; need Bs[k][n] = Bm[n0+n][k0+k]
            float4 bv = *(const float4*)(Bm + (size_t)(n0 + arow) * K + k0 + acol);
            Bs[acol+0][arow] = bv.x; Bs[acol+1][arow] = bv.y;
            Bs[acol+2][arow] = bv.z; Bs[acol+3][arow] = bv.w;
        }
        __syncthreads();

        #pragma unroll
        for (int k = 0; k < BK; k++) {
            float4 ra0 = *(const float4*)&As[k][ty * 8];
            float4 ra1 = *(const float4*)&As[k][ty * 8 + 4];
            float4 rb  = *(const float4*)&Bs[k][tx * 4];
            float ra[8] = {ra0.x, ra0.y, ra0.z, ra0.w, ra1.x, ra1.y, ra1.z, ra1.w};
            float rv[4] = {rb.x, rb.y, rb.z, rb.w};
            #pragma unroll
            for (int i = 0; i < 8; i++)
                #pragma unroll
                for (int j = 0; j < 4; j++)
                    acc[i][j] += ra[i] * rv[j];
        }
        __syncthreads();
    }

    #pragma unroll
    for (int i = 0; i < 8; i++) {
        const int m = m0 + ty * 8 + i;
        #pragma unroll
        for (int j = 0; j < 4; j++) {
            const int n = n0 + tx * 4 + j;
            float v = acc[i][j];
            if (EPI == 1) {
                v += Ay[b * NN + m] + Ax[b * NN + n];
                v = (v > 0.f) ? v : ALPHAc * v;
                v = (adj[(size_t)b * NN * NN + (size_t)m * NN + n] > 0) ? v : NEGc;
            }
            C[(size_t)m * N + n] = v;
        }
    }
}

// --------- Ax = h@a1, Ay = h@a2, e1[e] = feat row . L_w[e] (warp/row) -------
__global__ void small1_k(const float* __restrict__ h, const float* __restrict__ feat,
                         const float* __restrict__ a1, const float* __restrict__ a2,
                         const float* __restrict__ Lw,
                         float* __restrict__ Ax, float* __restrict__ Ay,
                         float* __restrict__ e1)
{
    const int warp = (blockIdx.x * blockDim.x + threadIdx.x) >> 5;
    const int lane = threadIdx.x & 31;
    if (warp >= MTOT) return;

    const float* hr = h + (size_t)warp * FOUTx;
    float sx = 0.f, sy = 0.f;
    for (int k = lane; k < FOUTx; k += 32) {
        const float f = hr[k];
        sx += f * a1[k];
        sy += f * a2[k];
    }
    const float* fr = feat + (size_t)warp * FINx;
    float acc[5] = {0.f, 0.f, 0.f, 0.f, 0.f};
    for (int k = lane; k < FINx; k += 32) {
        const float f = fr[k];
        #pragma unroll
        for (int e = 0; e < 5; e++) acc[e] += f * Lw[e * FINx + k];
    }
    #pragma unroll
    for (int off = 16; off; off >>= 1) {
        sx += __shfl_xor_sync(0xffffffffu, sx, off);
        sy += __shfl_xor_sync(0xffffffffu, sy, off);
        #pragma unroll
        for (int e = 0; e < 5; e++) acc[e] += __shfl_xor_sync(0xffffffffu, acc[e], off);
    }
    if (lane == 0) {
        Ax[warp] = sx;
        Ay[warp] = sy;
        #pragma unroll
        for (int e = 0; e < 5; e++) e1[warp * 8 + e] = acc[e];
    }
}

// --------- e2[e] = feat_agg row . R_w[e] -----------------------------------
__global__ void small2_k(const float* __restrict__ fa, const float* __restrict__ Rw,
                         float* __restrict__ e2)
{
    const int warp = (blockIdx.x * blockDim.x + threadIdx.x) >> 5;
    const int lane = threadIdx.x & 31;
    if (warp >= MTOT) return;

    const float* fr = fa + (size_t)warp * FINx;
    float acc[5] = {0.f, 0.f, 0.f, 0.f, 0.f};
    for (int k = lane; k < FINx; k += 32) {
        const float f = fr[k];
        #pragma unroll
        for (int e = 0; e < 5; e++) acc[e] += f * Rw[e * FINx + k];
    }
    #pragma unroll
    for (int off = 16; off; off >>= 1) {
        #pragma unroll
        for (int e = 0; e < 5; e++) acc[e] += __shfl_xor_sync(0xffffffffu, acc[e], off);
    }
    if (lane == 0) {
        #pragma unroll
        for (int e = 0; e < 5; e++) e2[warp * 8 + e] = acc[e];
    }
}

// --------- row softmax over N=2048, in place --------------------------------
__global__ void __launch_bounds__(256)
softmax_k(float* __restrict__ S)
{
    float* p = S + (size_t)blockIdx.x * NN;
    const int t = threadIdx.x;
    float v[8];
    float mx = -3.4e38f;
    #pragma unroll
    for (int i = 0; i < 8; i++) { v[i] = p[t + i * 256]; mx = fmaxf(mx, v[i]); }

    __shared__ float red[256];
    red[t] = mx; __syncthreads();
    #pragma unroll
    for (int s = 128; s > 0; s >>= 1) {
        if (t < s) red[t] = fmaxf(red[t], red[t + s]);
        __syncthreads();
    }
    mx = red[0];
    __syncthreads();

    float sum = 0.f;
    #pragma unroll
    for (int i = 0; i < 8; i++) { v[i] = __expf(v[i] - mx); sum += v[i]; }
    red[t] = sum; __syncthreads();
    #pragma unroll
    for (int s = 128; s > 0; s >>= 1) {
        if (t < s) red[t] += red[t + s];
        __syncthreads();
    }
    const float inv = 1.0f / red[0];
    #pragma unroll
    for (int i = 0; i < 8; i++) p[t + i * 256] = v[i] * inv;
}

// --------- out = h1 + h2 + e1^T B_w[o] e2 ----------------------------------
__global__ void __launch_bounds__(256)
final_k(const float* __restrict__ h1, const float* __restrict__ h2,
        const float* __restrict__ e1, const float* __restrict__ e2,
        const float* __restrict__ Bw, float* __restrict__ out)
{
    const int m = blockIdx.x;
    const int o = threadIdx.x;   // 0..255
    __shared__ float s1[8], s2[8];
    if (o < 5) { s1[o] = e1[m * 8 + o]; s2[o] = e2[m * 8 + o]; }
    __syncthreads();

    const float* bw = Bw + o * 25;
    float s = 0.f;
    #pragma unroll
    for (int i = 0; i < 5; i++) {
        const float ei = s1[i];
        #pragma unroll
        for (int j = 0; j < 5; j++) s += ei * bw[i * 5 + j] * s2[j];
    }
    const size_t idx = (size_t)m * FOUTx + o;
    out[idx] = h1[idx] + h2[idx] + s;
}

// ---------------------------------------------------------------------------
extern "C" void kernel_launch(void* const* d_in, const int* in_sizes, int n_in,
                              void* d_out, int out_size)
{
    const float* feat = (const float*)d_in[0];
    const int*   adj  = (const int*)  d_in[1];
    const float* W    = (const float*)d_in[2];
    const float* W1   = (const float*)d_in[3];
    const float* W2   = (const float*)d_in[4];
    const float* a1   = (const float*)d_in[5];
    const float* a2   = (const float*)d_in[6];
    const float* a12  = (const float*)d_in[7];
    const float* Lw   = (const float*)d_in[8];
    const float* Rw   = (const float*)d_in[9];
    const float* Bw   = (const float*)d_in[10];
    float* out = (float*)d_out;

    float *h, *h1, *g, *h2, *Ax, *Ay, *e1, *e2, *S, *fa;
    cudaGetSymbolAddress((void**)&h,  g_h);
    cudaGetSymbolAddress((void**)&h1, g_h1);
    cudaGetSymbolAddress((void**)&g,  g_g);
    cudaGetSymbolAddress((void**)&h2, g_h2);
    cudaGetSymbolAddress((void**)&Ax, g_Ax);
    cudaGetSymbolAddress((void**)&Ay, g_Ay);
    cudaGetSymbolAddress((void**)&e1, g_e1);
    cudaGetSymbolAddress((void**)&e2, g_e2);
    cudaGetSymbolAddress((void**)&S,  g_S);
    cudaGetSymbolAddress((void**)&fa, g_fa);

    const dim3 blk(256);

    // h = feat @ W ; h1 = feat @ W1
    gemm_k<false,0><<<dim3(FOUTx/64, MTOT/128, 1), blk>>>(
        feat, W,  h,  MTOT, FOUTx, FINx, 0, 0, 0, nullptr, nullptr, nullptr);
    gemm_k<false,0><<<dim3(FOUTx/64, MTOT/128, 1), blk>>>(
        feat, W1, h1, MTOT, FOUTx, FINx, 0, 0, 0, nullptr, nullptr, nullptr);

    // Ax, Ay, e1
    small1_k<<<MTOT/8, 256>>>(h, feat, a1, a2, Lw, Ax, Ay, e1);

    // g = h @ a12
    gemm_k<false,0><<<dim3(FOUTx/64, MTOT/128, 1), blk>>>(
        h, a12, g, MTOT, FOUTx, FOUTx, 0, 0, 0, nullptr, nullptr, nullptr);

    // S[b,i,j] = leaky(Ax[j]+Ay[i]+g_i.h_j) masked by adj  (batched NT GEMM)
    gemm_k<true,1><<<dim3(NN/64, NN/128, Bn), blk>>>(
        g, h, S, NN, NN, FOUTx,
        (size_t)NN*FOUTx, (size_t)NN*FOUTx, (size_t)NN*NN, Ax, Ay, adj);

    // row softmax (in place)
    softmax_k<<<MTOT, 256>>>(S);

    // feat_agg = P @ feat  (batched NN GEMM)
    gemm_k<false,0><<<dim3(FINx/64, NN/128, Bn), blk>>>(
        S, feat, fa, NN, FINx, NN,
        (size_t)NN*NN, (size_t)NN*FINx, (size_t)NN*FINx, nullptr, nullptr, nullptr);

    // e2
    small2_k<<<MTOT/8, 256>>>(fa, Rw, e2);

    // h2 = feat_agg @ W2
    gemm_k<false,0><<<dim3(FOUTx/64, MTOT/128, 1), blk>>>(
        fa, W2, h2, MTOT, FOUTx, FINx, 0, 0, 0, nullptr, nullptr, nullptr);

    // out = h1 + h2 + bilinear(e1, B_w, e2)
    final_k<<<MTOT, 256>>>(h1, h2, e1, e2, Bw, out);
}

// round 6
// speedup vs baseline: 1.0564x; 1.0018x over previous
#include <cuda_runtime.h>

// Problem constants
#define Bn    8
#define NN    2048
#define FINx  512
#define FOUTx 256
#define MTOT  (Bn*NN)          // 16384
#define ALPHAc 0.2f
#define NEGc  (-9e15f)

// ---------------- scratch (device globals: allocation-free) ----------------
__device__ float g_h [MTOT*FOUTx];            // feat@W
__device__ float g_h1[MTOT*FOUTx];            // feat@W1
__device__ float g_g [MTOT*FOUTx];            // h@a12
__device__ float g_h2[MTOT*FOUTx];            // fa@W2
__device__ float g_Ax[MTOT];
__device__ float g_Ay[MTOT];
__device__ float g_e1[MTOT*8];
__device__ float g_e2[MTOT*8];
__device__ float g_S [(size_t)Bn*NN*NN];      // logits / probs (134 MB)
__device__ float g_fa[(size_t)MTOT*FINx];     // feat_agg

// ---------------- generic tiled SGEMM: C = A @ B (or A @ B^T) --------------
// BM=128, BN=64, BK=16, 256 threads, 8x4 microtile.
// EPI==1: scores epilogue (+Ay[row] +Ax[col], leaky relu, adj mask).
template<bool TRANSB, int EPI>
__global__ void __launch_bounds__(256)
gemm_k(const float* __restrict__ A, const float* __restrict__ Bm,
       float* __restrict__ C, int M, int N, int K,
       size_t sA, size_t sB, size_t sC,
       const float* __restrict__ Ax, const float* __restrict__ Ay,
       const int* __restrict__ adj)
{
    constexpr int BM = 128, BN = 64, BK = 16;
    __shared__ float As[BK][BM + 4];
    __shared__ float Bs[BK][BN + 4];

    const int b = blockIdx.z;
    A  += (size_t)b * sA;
    Bm += (size_t)b * sB;
    C  += (size_t)b * sC;

    const int m0 = blockIdx.y * BM;
    const int n0 = blockIdx.x * BN;
    const int tid = threadIdx.x;
    const int tx = tid & 15;          // 0..15 -> 4 cols each
    const int ty = tid >> 4;          // 0..15 -> 8 rows each
    const int arow = tid >> 2;        // 0..63
    const int acol = (tid & 3) * 4;   // 0,4,8,12
    const int brow = tid >> 4;        // 0..15
    const int bcol = (tid & 15) * 4;  // 0..60

    float acc[8][4] = {};

    for (int k0 = 0; k0 < K; k0 += BK) {
        // A tile: 128 rows x 16 cols, two float4 per thread
        float4 a0  = *(const float4*)(A + (size_t)(m0 + arow)      * K + k0 + acol);
        float4 a1v = *(const float4*)(A + (size_t)(m0 + arow + 64) * K + k0 + acol);
        As[acol+0][arow]    = a0.x;  As[acol+1][arow]    = a0.y;
        As[acol+2][arow]    = a0.z;  As[acol+3][arow]    = a0.w;
        As[acol+0][arow+64] = a1v.x; As[acol+1][arow+64] = a1v.y;
        As[acol+2][arow+64] = a1v.z; As[acol+3][arow+64] = a1v.w;

        if (!TRANSB) {
            // B tile: 16 rows x 64 cols
            float4 bv = *(const float4*)(Bm + (size_t)(k0 + brow) * N + n0 + bcol);
            Bs[brow][bcol+0] = bv.x; Bs[brow][bcol+1] = bv.y;
            Bs[brow][bcol+2] = bv.z; Bs[brow][bcol+3] = bv.w;
        } else {
            // B is N x K row-major; need Bs[k][n] = Bm[n0+n][k0+k]
            float4 bv = *(const float4*)(Bm + (size_t)(n0 + arow) * K + k0 + acol);
            Bs[acol+0][arow] = bv.x; Bs[acol+1][arow] = bv.y;
            Bs[acol+2][arow] = bv.z; Bs[acol+3][arow] = bv.w;
        }
        __syncthreads();

        #pragma unroll
        for (int k = 0; k < BK; k++) {
            float4 ra0 = *(const float4*)&As[k][ty * 8];
            float4 ra1 = *(const float4*)&As[k][ty * 8 + 4];
            float4 rb  = *(const float4*)&Bs[k][tx * 4];
            float ra[8] = {ra0.x, ra0.y, ra0.z, ra0.w, ra1.x, ra1.y, ra1.z, ra1.w};
            float rv[4] = {rb.x, rb.y, rb.z, rb.w};
            #pragma unroll
            for (int i = 0; i < 8; i++)
                #pragma unroll
                for (int j = 0; j < 4; j++)
                    acc[i][j] += ra[i] * rv[j];
        }
        __syncthreads();
    }

    #pragma unroll
    for (int i = 0; i < 8; i++) {
        const int m = m0 + ty * 8 + i;
        #pragma unroll
        for (int j = 0; j < 4; j++) {
            const int n = n0 + tx * 4 + j;
            float v = acc[i][j];
            if (EPI == 1) {
                v += Ay[b * NN + m] + Ax[b * NN + n];
                v = (v > 0.f) ? v : ALPHAc * v;
                v = (adj[(size_t)b * NN * NN + (size_t)m * NN + n] > 0) ? v : NEGc;
            }
            C[(size_t)m * N + n] = v;
        }
    }
}

// --------- Ax = h@a1, Ay = h@a2, e1[e] = feat row . L_w[e] (warp/row) -------
__global__ void small1_k(const float* __restrict__ h, const float* __restrict__ feat,
                         const float* __restrict__ a1, const float* __restrict__ a2,
                         const float* __restrict__ Lw,
                         float* __restrict__ Ax, float* __restrict__ Ay,
                         float* __restrict__ e1)
{
    const int warp = (blockIdx.x * blockDim.x + threadIdx.x) >> 5;
    const int lane = threadIdx.x & 31;
    if (warp >= MTOT) return;

    const float* hr = h + (size_t)warp * FOUTx;
    float sx = 0.f, sy = 0.f;
    for (int k = lane; k < FOUTx; k += 32) {
        const float f = hr[k];
        sx += f * a1[k];
        sy += f * a2[k];
    }
    const float* fr = feat + (size_t)warp * FINx;
    float acc[5] = {0.f, 0.f, 0.f, 0.f, 0.f};
    for (int k = lane; k < FINx; k += 32) {
        const float f = fr[k];
        #pragma unroll
        for (int e = 0; e < 5; e++) acc[e] += f * Lw[e * FINx + k];
    }
    #pragma unroll
    for (int off = 16; off; off >>= 1) {
        sx += __shfl_xor_sync(0xffffffffu, sx, off);
        sy += __shfl_xor_sync(0xffffffffu, sy, off);
        #pragma unroll
        for (int e = 0; e < 5; e++) acc[e] += __shfl_xor_sync(0xffffffffu, acc[e], off);
    }
    if (lane == 0) {
        Ax[warp] = sx;
        Ay[warp] = sy;
        #pragma unroll
        for (int e = 0; e < 5; e++) e1[warp * 8 + e] = acc[e];
    }
}

// --------- e2[e] = feat_agg row . R_w[e] -----------------------------------
__global__ void small2_k(const float* __restrict__ fa, const float* __restrict__ Rw,
                         float* __restrict__ e2)
{
    const int warp = (blockIdx.x * blockDim.x + threadIdx.x) >> 5;
    const int lane = threadIdx.x & 31;
    if (warp >= MTOT) return;

    const float* fr = fa + (size_t)warp * FINx;
    float acc[5] = {0.f, 0.f, 0.f, 0.f, 0.f};
    for (int k = lane; k < FINx; k += 32) {
        const float f = fr[k];
        #pragma unroll
        for (int e = 0; e < 5; e++) acc[e] += f * Rw[e * FINx + k];
    }
    #pragma unroll
    for (int off = 16; off; off >>= 1) {
        #pragma unroll
        for (int e = 0; e < 5; e++) acc[e] += __shfl_xor_sync(0xffffffffu, acc[e], off);
    }
    if (lane == 0) {
        #pragma unroll
        for (int e = 0; e < 5; e++) e2[warp * 8 + e] = acc[e];
    }
}

// --------- row softmax over N=2048, in place --------------------------------
__global__ void __launch_bounds__(256)
softmax_k(float* __restrict__ S)
{
    float* p = S + (size_t)blockIdx.x * NN;
    const int t = threadIdx.x;
    float v[8];
    float mx = -3.4e38f;
    #pragma unroll
    for (int i = 0; i < 8; i++) { v[i] = p[t + i * 256]; mx = fmaxf(mx, v[i]); }

    __shared__ float red[256];
    red[t] = mx; __syncthreads();
    #pragma unroll
    for (int s = 128; s > 0; s >>= 1) {
        if (t < s) red[t] = fmaxf(red[t], red[t + s]);
        __syncthreads();
    }
    mx = red[0];
    __syncthreads();

    float sum = 0.f;
    #pragma unroll
    for (int i = 0; i < 8; i++) { v[i] = __expf(v[i] - mx); sum += v[i]; }
    red[t] = sum; __syncthreads();
    #pragma unroll
    for (int s = 128; s > 0; s >>= 1) {
        if (t < s) red[t] += red[t + s];
        __syncthreads();
    }
    const float inv = 1.0f / red[0];
    #pragma unroll
    for (int i = 0; i < 8; i++) p[t + i * 256] = v[i] * inv;
}

// --------- out = h1 + h2 + e1^T B_w[o] e2 ----------------------------------
__global__ void __launch_bounds__(256)
final_k(const float* __restrict__ h1, const float* __restrict__ h2,
        const float* __restrict__ e1, const float* __restrict__ e2,
        const float* __restrict__ Bw, float* __restrict__ out)
{
    const int m = blockIdx.x;
    const int o = threadIdx.x;   // 0..255
    __shared__ float s1[8], s2[8];
    if (o < 5) { s1[o] = e1[m * 8 + o]; s2[o] = e2[m * 8 + o]; }
    __syncthreads();

    const float* bw = Bw + o * 25;
    float s = 0.f;
    #pragma unroll
    for (int i = 0; i < 5; i++) {
        const float ei = s1[i];
        #pragma unroll
        for (int j = 0; j < 5; j++) s += ei * bw[i * 5 + j] * s2[j];
    }
    const size_t idx = (size_t)m * FOUTx + o;
    out[idx] = h1[idx] + h2[idx] + s;
}

// ---------------------------------------------------------------------------
extern "C" void kernel_launch(void* const* d_in, const int* in_sizes, int n_in,
                              void* d_out, int out_size)
{
    const float* feat = (const float*)d_in[0];
    const int*   adj  = (const int*)  d_in[1];
    const float* W    = (const float*)d_in[2];
    const float* W1   = (const float*)d_in[3];
    const float* W2   = (const float*)d_in[4];
    const float* a1   = (const float*)d_in[5];
    const float* a2   = (const float*)d_in[6];
    const float* a12  = (const float*)d_in[7];
    const float* Lw   = (const float*)d_in[8];
    const float* Rw   = (const float*)d_in[9];
    const float* Bw   = (const float*)d_in[10];
    float* out = (float*)d_out;

    float *h, *h1, *g, *h2, *Ax, *Ay, *e1, *e2, *S, *fa;
    cudaGetSymbolAddress((void**)&h,  g_h);
    cudaGetSymbolAddress((void**)&h1, g_h1);
    cudaGetSymbolAddress((void**)&g,  g_g);
    cudaGetSymbolAddress((void**)&h2, g_h2);
    cudaGetSymbolAddress((void**)&Ax, g_Ax);
    cudaGetSymbolAddress((void**)&Ay, g_Ay);
    cudaGetSymbolAddress((void**)&e1, g_e1);
    cudaGetSymbolAddress((void**)&e2, g_e2);
    cudaGetSymbolAddress((void**)&S,  g_S);
    cudaGetSymbolAddress((void**)&fa, g_fa);

    const dim3 blk(256);

    // h = feat @ W ; h1 = feat @ W1
    gemm_k<false,0><<<dim3(FOUTx/64, MTOT/128, 1), blk>>>(
        feat, W,  h,  MTOT, FOUTx, FINx, 0, 0, 0, nullptr, nullptr, nullptr);
    gemm_k<false,0><<<dim3(FOUTx/64, MTOT/128, 1), blk>>>(
        feat, W1, h1, MTOT, FOUTx, FINx, 0, 0, 0, nullptr, nullptr, nullptr);

    // Ax, Ay, e1
    small1_k<<<MTOT/8, 256>>>(h, feat, a1, a2, Lw, Ax, Ay, e1);

    // g = h @ a12
    gemm_k<false,0><<<dim3(FOUTx/64, MTOT/128, 1), blk>>>(
        h, a12, g, MTOT, FOUTx, FOUTx, 0, 0, 0, nullptr, nullptr, nullptr);

    // S[b,i,j] = leaky(Ax[j]+Ay[i]+g_i.h_j) masked by adj  (batched NT GEMM)
    gemm_k<true,1><<<dim3(NN/64, NN/128, Bn), blk>>>(
        g, h, S, NN, NN, FOUTx,
        (size_t)NN*FOUTx, (size_t)NN*FOUTx, (size_t)NN*NN, Ax, Ay, adj);

    // row softmax (in place)
    softmax_k<<<MTOT, 256>>>(S);

    // feat_agg = P @ feat  (batched NN GEMM)
    gemm_k<false,0><<<dim3(FINx/64, NN/128, Bn), blk>>>(
        S, feat, fa, NN, FINx, NN,
        (size_t)NN*NN, (size_t)NN*FINx, (size_t)NN*FINx, nullptr, nullptr, nullptr);

    // e2
    small2_k<<<MTOT/8, 256>>>(fa, Rw, e2);

    // h2 = feat_agg @ W2
    gemm_k<false,0><<<dim3(FOUTx/64, MTOT/128, 1), blk>>>(
        fa, W2, h2, MTOT, FOUTx, FINx, 0, 0, 0, nullptr, nullptr, nullptr);

    // out = h1 + h2 + bilinear(e1, B_w, e2)
    final_k<<<MTOT, 256>>>(h1, h2, e1, e2, Bw, out);
}

// round 7
// speedup vs baseline: 1.2202x; 1.1551x over previous
#include <cuda_runtime.h>

// Problem constants
#define Bn    8
#define NN    2048
#define FINx  512
#define FOUTx 256
#define MTOT  (Bn*NN)          // 16384
#define ALPHAc 0.2f
#define NEGc  (-9e15f)

// ---------------- scratch (device globals: allocation-free) ----------------
__device__ float g_h [MTOT*FOUTx];            // feat@W
__device__ float g_h1[MTOT*FOUTx];            // feat@W1
__device__ float g_g [MTOT*FOUTx];            // h@a12
__device__ float g_h2[MTOT*FOUTx];            // fa@W2
__device__ float g_Ax[MTOT];
__device__ float g_Ay[MTOT];
__device__ float g_e1[MTOT*8];
__device__ float g_e2[MTOT*8];
__device__ float g_S [(size_t)Bn*NN*NN];      // logits / probs (134 MB)
__device__ float g_fa[(size_t)MTOT*FINx];     // feat_agg

// ---------------- f32x2 (FFMA2) helpers -------------------------------------
__device__ __forceinline__ void lds_v2u64(unsigned long long &x, unsigned long long &y,
                                          const void* p) {
    unsigned a = (unsigned)__cvta_generic_to_shared(p);
    asm volatile("ld.shared.v2.u64 {%0,%1}, [%2];" : "=l"(x), "=l"(y) : "r"(a));
}
__device__ __forceinline__ unsigned long long splat2(float b) {
    unsigned long long r;
    asm("mov.b64 %0, {%1,%1};" : "=l"(r) : "f"(b));
    return r;
}
__device__ __forceinline__ void fma2(unsigned long long &acc, unsigned long long a,
                                     unsigned long long b) {
    asm("fma.rn.f32x2 %0, %1, %2, %0;" : "+l"(acc) : "l"(a), "l"(b));
}
__device__ __forceinline__ float2 unpack2(unsigned long long v) {
    float2 f;
    asm("mov.b64 {%0,%1}, %2;" : "=f"(f.x), "=f"(f.y) : "l"(v));
    return f;
}

// ---------------- generic tiled SGEMM: C = A @ B (or A @ B^T) --------------
// BM=128, BN=64, BK=16, 256 threads. Microtile 8 rows x 4 cols per thread,
// computed as 4 f32x2 row-pairs x 4 cols via packed fma.rn.f32x2 (FFMA2).
// EPI==1: scores epilogue (+Ay[row] +Ax[col], leaky relu, adj mask).
template<bool TRANSB, int EPI>
__global__ void __launch_bounds__(256)
gemm_k(const float* __restrict__ A, const float* __restrict__ Bm,
       float* __restrict__ C, int M, int N, int K,
       size_t sA, size_t sB, size_t sC,
       const float* __restrict__ Ax, const float* __restrict__ Ay,
       const int* __restrict__ adj)
{
    constexpr int BM = 128, BN = 64, BK = 16;
    __shared__ float As[BK][BM + 4];   // row stride 132 floats = 528B (16B aligned)
    __shared__ float Bs[BK][BN + 4];   // row stride 68  floats = 272B (16B aligned)

    const int b = blockIdx.z;
    A  += (size_t)b * sA;
    Bm += (size_t)b * sB;
    C  += (size_t)b * sC;

    const int m0 = blockIdx.y * BM;
    const int n0 = blockIdx.x * BN;
    const int tid = threadIdx.x;
    const int tx = tid & 15;          // 0..15 -> 4 cols each
    const int ty = tid >> 4;          // 0..15 -> 8 rows each
    const int arow = tid >> 2;        // 0..63
    const int acol = (tid & 3) * 4;   // 0,4,8,12
    const int brow = tid >> 4;        // 0..15
    const int bcol = (tid & 15) * 4;  // 0..60

    unsigned long long acc[4][4];
    #pragma unroll
    for (int r = 0; r < 4; r++)
        #pragma unroll
        for (int j = 0; j < 4; j++) acc[r][j] = 0ULL;

    // --- prefetch first tile into registers ---
    float4 a0, a1v, bv;
    a0  = *(const float4*)(A + (size_t)(m0 + arow)      * K + acol);
    a1v = *(const float4*)(A + (size_t)(m0 + arow + 64) * K + acol);
    if (!TRANSB) bv = *(const float4*)(Bm + (size_t)brow * N + n0 + bcol);
    else         bv = *(const float4*)(Bm + (size_t)(n0 + arow) * K + acol);

    for (int k0 = 0; k0 < K; k0 += BK) {
        // store prefetched tile to smem
        As[acol+0][arow]    = a0.x;  As[acol+1][arow]    = a0.y;
        As[acol+2][arow]    = a0.z;  As[acol+3][arow]    = a0.w;
        As[acol+0][arow+64] = a1v.x; As[acol+1][arow+64] = a1v.y;
        As[acol+2][arow+64] = a1v.z; As[acol+3][arow+64] = a1v.w;
        if (!TRANSB) {
            Bs[brow][bcol+0] = bv.x; Bs[brow][bcol+1] = bv.y;
            Bs[brow][bcol+2] = bv.z; Bs[brow][bcol+3] = bv.w;
        } else {
            Bs[acol+0][arow] = bv.x; Bs[acol+1][arow] = bv.y;
            Bs[acol+2][arow] = bv.z; Bs[acol+3][arow] = bv.w;
        }
        __syncthreads();

        // prefetch next tile (no smem touched -> overlaps with compute)
        const int kn = k0 + BK;
        if (kn < K) {
            a0  = *(const float4*)(A + (size_t)(m0 + arow)      * K + kn + acol);
            a1v = *(const float4*)(A + (size_t)(m0 + arow + 64) * K + kn + acol);
            if (!TRANSB) bv = *(const float4*)(Bm + (size_t)(kn + brow) * N + n0 + bcol);
            else         bv = *(const float4*)(Bm + (size_t)(n0 + arow) * K + kn + acol);
        }

        #pragma unroll
        for (int k = 0; k < BK; k++) {
            // A row-pairs: (a[2r], a[2r+1]) packed, free via ld.shared.v2.u64
            unsigned long long pa0, pa1, pa2, pa3;
            lds_v2u64(pa0, pa1, &As[k][ty * 8]);
            lds_v2u64(pa2, pa3, &As[k][ty * 8 + 4]);
            // B: 4 scalars, splat to pairs
            float4 rb = *(const float4*)&Bs[k][tx * 4];
            unsigned long long pb0 = splat2(rb.x), pb1 = splat2(rb.y);
            unsigned long long pb2 = splat2(rb.z), pb3 = splat2(rb.w);

            fma2(acc[0][0], pa0, pb0); fma2(acc[0][1], pa0, pb1);
            fma2(acc[0][2], pa0, pb2); fma2(acc[0][3], pa0, pb3);
            fma2(acc[1][0], pa1, pb0); fma2(acc[1][1], pa1, pb1);
            fma2(acc[1][2], pa1, pb2); fma2(acc[1][3], pa1, pb3);
            fma2(acc[2][0], pa2, pb0); fma2(acc[2][1], pa2, pb1);
            fma2(acc[2][2], pa2, pb2); fma2(acc[2][3], pa2, pb3);
            fma2(acc[3][0], pa3, pb0); fma2(acc[3][1], pa3, pb1);
            fma2(acc[3][2], pa3, pb2); fma2(acc[3][3], pa3, pb3);
        }
        __syncthreads();
    }

    // ---------------- epilogue (vectorized) ----------------
    const int nbase = n0 + tx * 4;
    #pragma unroll
    for (int r = 0; r < 4; r++) {
        float2 c0 = unpack2(acc[r][0]);
        float2 c1 = unpack2(acc[r][1]);
        float2 c2 = unpack2(acc[r][2]);
        float2 c3 = unpack2(acc[r][3]);
        float4 row_lo = make_float4(c0.x, c1.x, c2.x, c3.x);  // row 2r
        float4 row_hi = make_float4(c0.y, c1.y, c2.y, c3.y);  // row 2r+1
        const int m_lo = m0 + ty * 8 + 2 * r;

        if (EPI == 1) {
            const float ax0 = Ax[b * NN + nbase + 0];
            const float ax1 = Ax[b * NN + nbase + 1];
            const float ax2 = Ax[b * NN + nbase + 2];
            const float ax3 = Ax[b * NN + nbase + 3];
            #pragma unroll
            for (int h = 0; h < 2; h++) {
                const int m = m_lo + h;
                float4 v = h ? row_hi : row_lo;
                const float ay = Ay[b * NN + m];
                v.x += ay + ax0; v.y += ay + ax1; v.z += ay + ax2; v.w += ay + ax3;
                v.x = (v.x > 0.f) ? v.x : ALPHAc * v.x;
                v.y = (v.y > 0.f) ? v.y : ALPHAc * v.y;
                v.z = (v.z > 0.f) ? v.z : ALPHAc * v.z;
                v.w = (v.w > 0.f) ? v.w : ALPHAc * v.w;
                int4 ad = *(const int4*)(adj + (size_t)b * NN * NN + (size_t)m * NN + nbase);
                v.x = (ad.x > 0) ? v.x : NEGc;
                v.y = (ad.y > 0) ? v.y : NEGc;
                v.z = (ad.z > 0) ? v.z : NEGc;
                v.w = (ad.w > 0) ? v.w : NEGc;
                *(float4*)(C + (size_t)m * N + nbase) = v;
            }
        } else {
            *(float4*)(C + (size_t)m_lo       * N + nbase) = row_lo;
            *(float4*)(C + (size_t)(m_lo + 1) * N + nbase) = row_hi;
        }
    }
}

// --------- Ax = h@a1, Ay = h@a2, e1[e] = feat row . L_w[e] (warp/row) -------
__global__ void small1_k(const float* __restrict__ h, const float* __restrict__ feat,
                         const float* __restrict__ a1, const float* __restrict__ a2,
                         const float* __restrict__ Lw,
                         float* __restrict__ Ax, float* __restrict__ Ay,
                         float* __restrict__ e1)
{
    const int warp = (blockIdx.x * blockDim.x + threadIdx.x) >> 5;
    const int lane = threadIdx.x & 31;
    if (warp >= MTOT) return;

    const float* hr = h + (size_t)warp * FOUTx;
    float sx = 0.f, sy = 0.f;
    for (int k = lane; k < FOUTx; k += 32) {
        const float f = hr[k];
        sx += f * a1[k];
        sy += f * a2[k];
    }
    const float* fr = feat + (size_t)warp * FINx;
    float acc[5] = {0.f, 0.f, 0.f, 0.f, 0.f};
    for (int k = lane; k < FINx; k += 32) {
        const float f = fr[k];
        #pragma unroll
        for (int e = 0; e < 5; e++) acc[e] += f * Lw[e * FINx + k];
    }
    #pragma unroll
    for (int off = 16; off; off >>= 1) {
        sx += __shfl_xor_sync(0xffffffffu, sx, off);
        sy += __shfl_xor_sync(0xffffffffu, sy, off);
        #pragma unroll
        for (int e = 0; e < 5; e++) acc[e] += __shfl_xor_sync(0xffffffffu, acc[e], off);
    }
    if (lane == 0) {
        Ax[warp] = sx;
        Ay[warp] = sy;
        #pragma unroll
        for (int e = 0; e < 5; e++) e1[warp * 8 + e] = acc[e];
    }
}

// --------- e2[e] = feat_agg row . R_w[e] -----------------------------------
__global__ void small2_k(const float* __restrict__ fa, const float* __restrict__ Rw,
                         float* __restrict__ e2)
{
    const int warp = (blockIdx.x * blockDim.x + threadIdx.x) >> 5;
    const int lane = threadIdx.x & 31;
    if (warp >= MTOT) return;

    const float* fr = fa + (size_t)warp * FINx;
    float acc[5] = {0.f, 0.f, 0.f, 0.f, 0.f};
    for (int k = lane; k < FINx; k += 32) {
        const float f = fr[k];
        #pragma unroll
        for (int e = 0; e < 5; e++) acc[e] += f * Rw[e * FINx + k];
    }
    #pragma unroll
    for (int off = 16; off; off >>= 1) {
        #pragma unroll
        for (int e = 0; e < 5; e++) acc[e] += __shfl_xor_sync(0xffffffffu, acc[e], off);
    }
    if (lane == 0) {
        #pragma unroll
        for (int e = 0; e < 5; e++) e2[warp * 8 + e] = acc[e];
    }
}

// --------- row softmax over N=2048, in place --------------------------------
__global__ void __launch_bounds__(256)
softmax_k(float* __restrict__ S)
{
    float* p = S + (size_t)blockIdx.x * NN;
    const int t = threadIdx.x;
    float v[8];
    float mx = -3.4e38f;
    #pragma unroll
    for (int i = 0; i < 8; i++) { v[i] = p[t + i * 256]; mx = fmaxf(mx, v[i]); }

    __shared__ float red[256];
    red[t] = mx; __syncthreads();
    #pragma unroll
    for (int s = 128; s > 0; s >>= 1) {
        if (t < s) red[t] = fmaxf(red[t], red[t + s]);
        __syncthreads();
    }
    mx = red[0];
    __syncthreads();

    float sum = 0.f;
    #pragma unroll
    for (int i = 0; i < 8; i++) { v[i] = __expf(v[i] - mx); sum += v[i]; }
    red[t] = sum; __syncthreads();
    #pragma unroll
    for (int s = 128; s > 0; s >>= 1) {
        if (t < s) red[t] += red[t + s];
        __syncthreads();
    }
    const float inv = 1.0f / red[0];
    #pragma unroll
    for (int i = 0; i < 8; i++) p[t + i * 256] = v[i] * inv;
}

// --------- out = h1 + h2 + e1^T B_w[o] e2 ----------------------------------
__global__ void __launch_bounds__(256)
final_k(const float* __restrict__ h1, const float* __restrict__ h2,
        const float* __restrict__ e1, const float* __restrict__ e2,
        const float* __restrict__ Bw, float* __restrict__ out)
{
    const int m = blockIdx.x;
    const int o = threadIdx.x;   // 0..255
    __shared__ float s1[8], s2[8];
    if (o < 5) { s1[o] = e1[m * 8 + o]; s2[o] = e2[m * 8 + o]; }
    __syncthreads();

    const float* bw = Bw + o * 25;
    float s = 0.f;
    #pragma unroll
    for (int i = 0; i < 5; i++) {
        const float ei = s1[i];
        #pragma unroll
        for (int j = 0; j < 5; j++) s += ei * bw[i * 5 + j] * s2[j];
    }
    const size_t idx = (size_t)m * FOUTx + o;
    out[idx] = h1[idx] + h2[idx] + s;
}

// ---------------------------------------------------------------------------
extern "C" void kernel_launch(void* const* d_in, const int* in_sizes, int n_in,
                              void* d_out, int out_size)
{
    const float* feat = (const float*)d_in[0];
    const int*   adj  = (const int*)  d_in[1];
    const float* W    = (const float*)d_in[2];
    const float* W1   = (const float*)d_in[3];
    const float* W2   = (const float*)d_in[4];
    const float* a1   = (const float*)d_in[5];
    const float* a2   = (const float*)d_in[6];
    const float* a12  = (const float*)d_in[7];
    const float* Lw   = (const float*)d_in[8];
    const float* Rw   = (const float*)d_in[9];
    const float* Bw   = (const float*)d_in[10];
    float* out = (float*)d_out;

    float *h, *h1, *g, *h2, *Ax, *Ay, *e1, *e2, *S, *fa;
    cudaGetSymbolAddress((void**)&h,  g_h);
    cudaGetSymbolAddress((void**)&h1, g_h1);
    cudaGetSymbolAddress((void**)&g,  g_g);
    cudaGetSymbolAddress((void**)&h2, g_h2);
    cudaGetSymbolAddress((void**)&Ax, g_Ax);
    cudaGetSymbolAddress((void**)&Ay, g_Ay);
    cudaGetSymbolAddress((void**)&e1, g_e1);
    cudaGetSymbolAddress((void**)&e2, g_e2);
    cudaGetSymbolAddress((void**)&S,  g_S);
    cudaGetSymbolAddress((void**)&fa, g_fa);

    const dim3 blk(256);

    // h = feat @ W ; h1 = feat @ W1
    gemm_k<false,0><<<dim3(FOUTx/64, MTOT/128, 1), blk>>>(
        feat, W,  h,  MTOT, FOUTx, FINx, 0, 0, 0, nullptr, nullptr, nullptr);
    gemm_k<false,0><<<dim3(FOUTx/64, MTOT/128, 1), blk>>>(
        feat, W1, h1, MTOT, FOUTx, FINx, 0, 0, 0, nullptr, nullptr, nullptr);

    // Ax, Ay, e1
    small1_k<<<MTOT/8, 256>>>(h, feat, a1, a2, Lw, Ax, Ay, e1);

    // g = h @ a12
    gemm_k<false,0><<<dim3(FOUTx/64, MTOT/128, 1), blk>>>(
        h, a12, g, MTOT, FOUTx, FOUTx, 0, 0, 0, nullptr, nullptr, nullptr);

    // S[b,i,j] = leaky(Ax[j]+Ay[i]+g_i.h_j) masked by adj  (batched NT GEMM)
    gemm_k<true,1><<<dim3(NN/64, NN/128, Bn), blk>>>(
        g, h, S, NN, NN, FOUTx,
        (size_t)NN*FOUTx, (size_t)NN*FOUTx, (size_t)NN*NN, Ax, Ay, adj);

    // row softmax (in place)
    softmax_k<<<MTOT, 256>>>(S);

    // feat_agg = P @ feat  (batched NN GEMM)
    gemm_k<false,0><<<dim3(FINx/64, NN/128, Bn), blk>>>(
        S, feat, fa, NN, FINx, NN,
        (size_t)NN*NN, (size_t)NN*FINx, (size_t)NN*FINx, nullptr, nullptr, nullptr);

    // e2
    small2_k<<<MTOT/8, 256>>>(fa, Rw, e2);

    // h2 = feat_agg @ W2
    gemm_k<false,0><<<dim3(FOUTx/64, MTOT/128, 1), blk>>>(
        fa, W2, h2, MTOT, FOUTx, FINx, 0, 0, 0, nullptr, nullptr, nullptr);

    // out = h1 + h2 + bilinear(e1, B_w, e2)
    final_k<<<MTOT, 256>>>(h1, h2, e1, e2, Bw, out);
}